// round 2
// baseline (speedup 1.0000x reference)
#include <cuda_runtime.h>
#include <cstdint>

// ---------------------------------------------------------------------------
// Idefics3VisionEmbeddings:
//   out[b, p, d] = sum_k pixel_patch(b,p)[k] * conv_w[d][k] + conv_b[d]
//                  + pos_emb[position_id(b,p)][d]
// GEMM: M=21632 (=32*676), N=1152, K=588 (=3*14*14). All tile-exact.
// ---------------------------------------------------------------------------

namespace {
constexpr int kNPS   = 26;
constexpr int kPatch = 14;
constexpr int kB     = 32;
constexpr int kC     = 3;
constexpr int kHW    = 364;
constexpr int kD     = 1152;
constexpr int kP     = kNPS * kNPS;            // 676
constexpr int kK     = kC * kPatch * kPatch;   // 588
constexpr int kM     = kB * kP;                // 21632

constexpr int BM = 128, BN = 128, BK = 14;
constexpr int TM = 8, TN = 8;
constexpr int NTHREADS = 256;
constexpr int KT = kK / BK;                    // 42
}  // namespace

// Scratch for position ids (no cudaMalloc allowed).
__device__ int g_pos[kB * kP];

// ---------------------------------------------------------------------------
// Position-id kernel: replicates the reference fp32 math exactly.
//   boundaries[j] = (j+1)/26 (fp32 div)
//   frac = (p / nb) * (1 - 1e-6)   (fp32 div then mul)
//   id = #{ j : boundaries[j] <= frac }  (searchsorted side='right')
// Mask dtype auto-detect: byte 1 nonzero  => u8/bool layout (nb_w >= 13
// guarantees mask[0][0][1] == 1); byte 1 == 0 => int32 layout.
// ---------------------------------------------------------------------------
__global__ void pos_kernel(const unsigned char* __restrict__ mraw) {
    const int b = blockIdx.x;
    const int t = threadIdx.x;

    __shared__ int s_bh[kNPS];
    __shared__ int s_bw[kNPS];
    __shared__ int s_nbh, s_nbw;

    const bool is_u8 = (mraw[1] != 0);
    // element accessor for mask[b, i, j]
    auto mval = [&](int idx) -> int {
        return is_u8 ? (int)mraw[idx] : (int)mraw[4 * (size_t)idx];
    };
    const int base = b * kP;

    if (t == 0) {
        int nh = 0, nw = 0;
        for (int i = 0; i < kNPS; i++) nh += (mval(base + i * kNPS) != 0);
        for (int j = 0; j < kNPS; j++) nw += (mval(base + j) != 0);
        s_nbh = nh;
        s_nbw = nw;
    }
    __syncthreads();

    if (t < kNPS) {
        const float eps = 1.0f - 1e-6f;
        const float fh = ((float)t / (float)s_nbh) * eps;
        const float fw = ((float)t / (float)s_nbw) * eps;
        int ch = 0, cw = 0;
        #pragma unroll
        for (int j = 1; j < kNPS; j++) {
            const float bnd = (float)j / (float)kNPS;
            ch += (bnd <= fh) ? 1 : 0;
            cw += (bnd <= fw) ? 1 : 0;
        }
        s_bh[t] = ch;
        s_bw[t] = cw;
    }
    __syncthreads();

    for (int p = t; p < kP; p += blockDim.x) {
        const int ph = p / kNPS;
        const int pw = p - ph * kNPS;
        const int on = (mval(base + p) != 0);
        g_pos[base + p] = on ? (s_bh[ph] * kNPS + s_bw[pw]) : 0;
    }
}

// Packed dual-FMA (sm_103a): two fp32 FMAs per instruction, exact IEEE fp32.
__device__ __forceinline__ void ffma2(float2& d, float2 a, float2 b) {
    asm("fma.rn.f32x2 %0, %1, %2, %0;"
        : "+l"(*reinterpret_cast<unsigned long long*>(&d))
        : "l"(*reinterpret_cast<unsigned long long*>(&a)),
          "l"(*reinterpret_cast<unsigned long long*>(&b)));
}

// ---------------------------------------------------------------------------
// Implicit-GEMM patch-embed with fused bias + positional-embedding epilogue.
// Grid: (169, 9). Block: 256 threads, 8x8 microtile each.
// BK = 14 so each A-tile K-slice is 14 contiguous floats of one pixel row.
// ---------------------------------------------------------------------------
__global__ __launch_bounds__(NTHREADS, 2)
void gemm_kernel(const float* __restrict__ pix,
                 const float* __restrict__ wgt,
                 const float* __restrict__ bias,
                 const float* __restrict__ pe,
                 float* __restrict__ out) {
    __shared__ float As[BK][BM];
    __shared__ float Bs[BK][BN];

    const int tid = threadIdx.x;
    const int bm  = blockIdx.x;
    const int bn  = blockIdx.y;

    const int tx = tid & 15;
    const int ty = tid >> 4;

    // Tile-load mapping: 2 threads per row, each loads 7 contiguous floats.
    const int lrow = tid >> 1;          // 0..127
    const int lk   = (tid & 1) * 7;     // 0 or 7

    // A (im2col) source address for this thread's row.
    const int m   = bm * BM + lrow;
    const int b   = m / kP;
    const int rem = m - b * kP;
    const int ph  = rem / kNPS;
    const int pw  = rem - ph * kNPS;
    const float* apix = pix + (size_t)b * (kC * kHW * kHW)
                        + (ph * kPatch) * kHW + pw * kPatch + lk;

    // B (weights) source row.
    const int n = bn * BN + lrow;
    const float* wrow = wgt + (size_t)n * kK + lk;

    float2 acc[TM][TN / 2];
    #pragma unroll
    for (int i = 0; i < TM; i++)
        #pragma unroll
        for (int j = 0; j < TN / 2; j++) acc[i][j] = make_float2(0.f, 0.f);

    #pragma unroll 1
    for (int kt = 0; kt < KT; kt++) {
        const int c  = kt / kPatch;          // channel
        const int ky = kt - c * kPatch;      // row within patch
        const float* ap = apix + c * (kHW * kHW) + ky * kHW;
        const float* bp = wrow + kt * BK;

        float ar[7], br[7];
        #pragma unroll
        for (int i = 0; i < 7; i++) {
            ar[i] = ap[i];
            br[i] = bp[i];
        }
        __syncthreads();  // previous tile's compute done
        #pragma unroll
        for (int i = 0; i < 7; i++) {
            As[lk + i][lrow] = ar[i];
            Bs[lk + i][lrow] = br[i];
        }
        __syncthreads();  // tile visible

        #pragma unroll
        for (int kk = 0; kk < BK; kk++) {
            const float4 a0 = *reinterpret_cast<const float4*>(&As[kk][ty * TM]);
            const float4 a1 = *reinterpret_cast<const float4*>(&As[kk][ty * TM + 4]);
            const float4 b0 = *reinterpret_cast<const float4*>(&Bs[kk][tx * TN]);
            const float4 b1 = *reinterpret_cast<const float4*>(&Bs[kk][tx * TN + 4]);
            const float aa[8] = {a0.x, a0.y, a0.z, a0.w, a1.x, a1.y, a1.z, a1.w};
            float2 bb[4];
            bb[0] = make_float2(b0.x, b0.y);
            bb[1] = make_float2(b0.z, b0.w);
            bb[2] = make_float2(b1.x, b1.y);
            bb[3] = make_float2(b1.z, b1.w);
            #pragma unroll
            for (int i = 0; i < TM; i++) {
                const float2 ad = make_float2(aa[i], aa[i]);
                #pragma unroll
                for (int j = 0; j < TN / 2; j++) ffma2(acc[i][j], ad, bb[j]);
            }
        }
    }

    // Epilogue: + conv_b + pos_emb[position_id]
    const int mbase = bm * BM + ty * TM;
    const int nbase = bn * BN + tx * TN;
    #pragma unroll
    for (int i = 0; i < TM; i++) {
        const int mm  = mbase + i;
        const int pos = g_pos[mm];
        const float* per = pe + (size_t)pos * kD + nbase;
        float* orow = out + (size_t)mm * kD + nbase;
        #pragma unroll
        for (int j = 0; j < TN / 2; j++) {
            float2 v = acc[i][j];
            v.x += per[2 * j]     + bias[nbase + 2 * j];
            v.y += per[2 * j + 1] + bias[nbase + 2 * j + 1];
            *reinterpret_cast<float2*>(&orow[2 * j]) = v;
        }
    }
}

extern "C" void kernel_launch(void* const* d_in, const int* in_sizes, int n_in,
                              void* d_out, int out_size) {
    const float* pix          = (const float*)d_in[0];
    const unsigned char* mask = (const unsigned char*)d_in[1];
    const float* wgt          = (const float*)d_in[2];
    const float* bias         = (const float*)d_in[3];
    const float* pe           = (const float*)d_in[4];
    float* out                = (float*)d_out;

    pos_kernel<<<kB, 128>>>(mask);

    dim3 grid(kM / BM, kD / BN);  // (169, 9)
    gemm_kernel<<<grid, NTHREADS>>>(pix, wgt, bias, pe, out);
}

// round 4
// speedup vs baseline: 1.8021x; 1.8021x over previous
#include <cuda_runtime.h>
#include <cuda_bf16.h>
#include <cstdint>

// ===========================================================================
// Idefics3VisionEmbeddings via mma.sync bf16 (base sm_103 ISA).
//   out[m,n] = sum_k A[m,k]*W[n,k] + bias[n] + pos_emb[pos[m], n]
//   M=21632 (=169*128), N=1152 (=9*128), K=588 (pad 640)
// fp32 emulated with 3 bf16 MMAs: A=Ahi+Amid, W=Whi+Wmid,
//   D = Ahi*Whi + Ahi*Wmid + Amid*Whi    (error ~2^-18)
// ===========================================================================

namespace {
constexpr int kNPS = 26, kPatch = 14, kB = 32, kC = 3, kHW = 364, kD = 1152;
constexpr int kP = kNPS * kNPS;           // 676
constexpr int kK = kC * kPatch * kPatch;  // 588
constexpr int kM = kB * kP;               // 21632
constexpr int kKpad = 640;

constexpr int BM = 128, BN = 128, BK = 32;
constexpr int NCHUNK = kKpad / BK;        // 20

// smem: rows of 32 bf16 padded to 40 (80 B) -> conflict-free ldmatrix
constexpr int ROWB = 80;
constexpr int ARR = 128 * ROWB;           // 10240 B per array
constexpr int STAGE = 4 * ARR;            // Ahi, Amid, Bhi, Bmid = 40960 B
constexpr int NSTG = 3;
constexpr int SMEM_SZ = NSTG * STAGE;     // 122880
}  // namespace

// -------------------- device scratch (no cudaMalloc allowed) ---------------
__device__ __align__(256) __nv_bfloat16 g_Ahi[(size_t)kM * kKpad];
__device__ __align__(256) __nv_bfloat16 g_Amid[(size_t)kM * kKpad];
__device__ __align__(256) __nv_bfloat16 g_Whi[(size_t)kD * kKpad];
__device__ __align__(256) __nv_bfloat16 g_Wmid[(size_t)kD * kKpad];
__device__ int g_pos[kM];

// -------------------- helpers ----------------------------------------------
__device__ __forceinline__ uint32_t smem_u32(const void* p) {
    uint32_t a;
    asm("{ .reg .u64 t; cvta.to.shared.u64 t, %1; cvt.u32.u64 %0, t; }"
        : "=r"(a) : "l"(p));
    return a;
}
__device__ __forceinline__ void cp16(uint32_t dst, const void* src) {
    asm volatile("cp.async.cg.shared.global [%0], [%1], 16;"
                 :: "r"(dst), "l"(src) : "memory");
}
__device__ __forceinline__ void ldsm4(uint32_t* r, uint32_t addr) {
    asm volatile("ldmatrix.sync.aligned.m8n8.x4.shared.b16 {%0,%1,%2,%3}, [%4];"
                 : "=r"(r[0]), "=r"(r[1]), "=r"(r[2]), "=r"(r[3]) : "r"(addr));
}
__device__ __forceinline__ void mma16816(float* c, const uint32_t* a,
                                         const uint32_t* b) {
    asm volatile(
        "mma.sync.aligned.m16n8k16.row.col.f32.bf16.bf16.f32 "
        "{%0,%1,%2,%3}, {%4,%5,%6,%7}, {%8,%9}, {%0,%1,%2,%3};"
        : "+f"(c[0]), "+f"(c[1]), "+f"(c[2]), "+f"(c[3])
        : "r"(a[0]), "r"(a[1]), "r"(a[2]), "r"(a[3]), "r"(b[0]), "r"(b[1]));
}

// ---------------------------------------------------------------------------
// Position ids (exact fp32 replica of the reference). Mask dtype auto-detect.
// ---------------------------------------------------------------------------
__global__ void pos_kernel(const unsigned char* __restrict__ mraw) {
    const int b = blockIdx.x;
    const int t = threadIdx.x;
    __shared__ int s_bh[kNPS], s_bw[kNPS];
    __shared__ int s_nbh, s_nbw;

    const bool is_u8 = (mraw[1] != 0);
    auto mval = [&](int idx) -> int {
        return is_u8 ? (int)mraw[idx] : (int)mraw[4 * (size_t)idx];
    };
    const int base = b * kP;
    if (t == 0) {
        int nh = 0, nw = 0;
        for (int i = 0; i < kNPS; i++) nh += (mval(base + i * kNPS) != 0);
        for (int j = 0; j < kNPS; j++) nw += (mval(base + j) != 0);
        s_nbh = nh; s_nbw = nw;
    }
    __syncthreads();
    if (t < kNPS) {
        const float eps = 1.0f - 1e-6f;
        const float fh = ((float)t / (float)s_nbh) * eps;
        const float fw = ((float)t / (float)s_nbw) * eps;
        int ch = 0, cw = 0;
        #pragma unroll
        for (int j = 1; j < kNPS; j++) {
            const float bnd = (float)j / (float)kNPS;
            ch += (bnd <= fh) ? 1 : 0;
            cw += (bnd <= fw) ? 1 : 0;
        }
        s_bh[t] = ch; s_bw[t] = cw;
    }
    __syncthreads();
    for (int p = t; p < kP; p += blockDim.x) {
        const int ph = p / kNPS;
        const int pw = p - ph * kNPS;
        g_pos[base + p] = (mval(base + p) != 0) ? (s_bh[ph] * kNPS + s_bw[pw]) : 0;
    }
}

// ---------------------------------------------------------------------------
// Prep: im2col A -> bf16 hi/mid [kM, kKpad]; W -> hi/mid [kD, kKpad].
// ---------------------------------------------------------------------------
__global__ void prep_a(const float* __restrict__ pix) {
    const int total = kM * kKpad;
    for (int idx = blockIdx.x * blockDim.x + threadIdx.x; idx < total;
         idx += gridDim.x * blockDim.x) {
        const int m = idx / kKpad;
        const int k = idx - m * kKpad;
        float v = 0.f;
        if (k < kK) {
            const int b = m / kP;
            const int rem = m - b * kP;
            const int ph = rem / kNPS;
            const int pw = rem - ph * kNPS;
            const int c = k / (kPatch * kPatch);
            const int r = k - c * (kPatch * kPatch);
            const int ky = r / kPatch;
            const int kx = r - ky * kPatch;
            v = pix[(size_t)b * (kC * kHW * kHW) + (size_t)c * (kHW * kHW)
                    + (ph * kPatch + ky) * kHW + (pw * kPatch + kx)];
        }
        const __nv_bfloat16 hi = __float2bfloat16_rn(v);
        g_Ahi[idx] = hi;
        g_Amid[idx] = __float2bfloat16_rn(v - __bfloat162float(hi));
    }
}

__global__ void prep_w(const float* __restrict__ wgt) {
    const int total = kD * kKpad;
    for (int idx = blockIdx.x * blockDim.x + threadIdx.x; idx < total;
         idx += gridDim.x * blockDim.x) {
        const int n = idx / kKpad;
        const int k = idx - n * kKpad;
        float v = (k < kK) ? wgt[(size_t)n * kK + k] : 0.f;
        const __nv_bfloat16 hi = __float2bfloat16_rn(v);
        g_Whi[idx] = hi;
        g_Wmid[idx] = __float2bfloat16_rn(v - __bfloat162float(hi));
    }
}

// ---------------------------------------------------------------------------
// GEMM: 128x128 tile, BK=32, 3-stage cp.async, 8 warps (warp tile 32x64).
// ---------------------------------------------------------------------------
__global__ void __launch_bounds__(256)
gemm_kernel(const float* __restrict__ bias,
            const float* __restrict__ pe,
            float* __restrict__ out) {
    extern __shared__ char smem[];
    const uint32_t sbase = smem_u32(smem);
    const int tid = threadIdx.x;
    const int wid = tid >> 5;
    const int lane = tid & 31;

    const int m0 = blockIdx.x * BM;
    const int n0 = blockIdx.y * BN;

    const int warp_m = (wid & 3) * 32;   // 4 warps along M
    const int warp_n = (wid >> 2) * 64;  // 2 warps along N

    // loader: thread t -> row t>>1, two 16B chunks (t&1)*2, (t&1)*2+1
    const int lrow = tid >> 1;
    const int lc0 = (tid & 1) * 2;
    const __nv_bfloat16* gAhi = g_Ahi + (size_t)(m0 + lrow) * kKpad;
    const __nv_bfloat16* gAmid = g_Amid + (size_t)(m0 + lrow) * kKpad;
    const __nv_bfloat16* gBhi = g_Whi + (size_t)(n0 + lrow) * kKpad;
    const __nv_bfloat16* gBmid = g_Wmid + (size_t)(n0 + lrow) * kKpad;

    auto load_chunk = [&](int j, int s) {
        const int k0 = j * BK;
        const uint32_t sb = sbase + s * STAGE + lrow * ROWB;
        #pragma unroll
        for (int q = 0; q < 2; q++) {
            const int c = lc0 + q;
            const uint32_t d = sb + c * 16;
            const int gk = k0 + c * 8;
            cp16(d,            gAhi + gk);
            cp16(d + ARR,      gAmid + gk);
            cp16(d + 2 * ARR,  gBhi + gk);
            cp16(d + 3 * ARR,  gBmid + gk);
        }
        asm volatile("cp.async.commit_group;" ::: "memory");
    };

    // ldmatrix per-thread offsets
    const int sel = lane >> 3, li = lane & 7;
    const int aRow = (sel & 1) * 8 + li;      // +8 rows on sel bit0
    const int aC16 = (sel >> 1) * 16;         // +16B (k+8) on sel bit1
    const int bRow = (sel >> 1) * 8 + li;     // +8 n-rows on sel bit1
    const int bC16 = (sel & 1) * 16;          // +16B (k+8) on sel bit0

    float acc[2][8][4];
    #pragma unroll
    for (int i = 0; i < 2; i++)
        #pragma unroll
        for (int j = 0; j < 8; j++)
            #pragma unroll
            for (int q = 0; q < 4; q++) acc[i][j][q] = 0.f;

    load_chunk(0, 0);
    load_chunk(1, 1);

    #pragma unroll 1
    for (int j = 0; j < NCHUNK; j++) {
        const int s = j % 3;
        if (j < NCHUNK - 1)
            asm volatile("cp.async.wait_group 1;" ::: "memory");
        else
            asm volatile("cp.async.wait_group 0;" ::: "memory");
        __syncthreads();

        if (j + 2 < NCHUNK) load_chunk(j + 2, (j + 2) % 3);

        const uint32_t st = sbase + s * STAGE;
        const uint32_t aBase = st + (warp_m + aRow) * ROWB + aC16;
        const uint32_t bBase = st + 2 * ARR + (warp_n + bRow) * ROWB + bC16;

        #pragma unroll
        for (int ks = 0; ks < 2; ks++) {
            uint32_t ah[2][4], am[2][4], bh[4][4], bm[4][4];
            #pragma unroll
            for (int mt = 0; mt < 2; mt++) {
                const uint32_t a = aBase + mt * 16 * ROWB + ks * 32;
                ldsm4(ah[mt], a);
                ldsm4(am[mt], a + ARR);
            }
            #pragma unroll
            for (int bt = 0; bt < 4; bt++) {
                const uint32_t b = bBase + bt * 16 * ROWB + ks * 32;
                ldsm4(bh[bt], b);
                ldsm4(bm[bt], b + ARR);
            }
            #pragma unroll
            for (int mt = 0; mt < 2; mt++)
                #pragma unroll
                for (int nt = 0; nt < 8; nt++) {
                    const int bt = nt >> 1, hp = (nt & 1) * 2;
                    mma16816(acc[mt][nt], ah[mt], &bh[bt][hp]);
                    mma16816(acc[mt][nt], ah[mt], &bm[bt][hp]);
                    mma16816(acc[mt][nt], am[mt], &bh[bt][hp]);
                }
        }
    }

    // ---------------- epilogue: + bias + pos_emb[pos[m]] --------------------
    const int r = lane >> 2, cg = lane & 3;
    #pragma unroll
    for (int mt = 0; mt < 2; mt++) {
        #pragma unroll
        for (int h = 0; h < 2; h++) {
            const int m = m0 + warp_m + mt * 16 + h * 8 + r;
            const float* per = pe + (size_t)g_pos[m] * kD;
            float* orow = out + (size_t)m * kD;
            #pragma unroll
            for (int nt = 0; nt < 8; nt++) {
                const int n = n0 + warp_n + nt * 8 + cg * 2;
                const float2 p = *reinterpret_cast<const float2*>(per + n);
                const float2 bv = *reinterpret_cast<const float2*>(bias + n);
                float2 v;
                v.x = acc[mt][nt][h * 2 + 0] + p.x + bv.x;
                v.y = acc[mt][nt][h * 2 + 1] + p.y + bv.y;
                *reinterpret_cast<float2*>(orow + n) = v;
            }
        }
    }
}

// ---------------------------------------------------------------------------
extern "C" void kernel_launch(void* const* d_in, const int* in_sizes, int n_in,
                              void* d_out, int out_size) {
    const float* pix          = (const float*)d_in[0];
    const unsigned char* mask = (const unsigned char*)d_in[1];
    const float* wgt          = (const float*)d_in[2];
    const float* bias         = (const float*)d_in[3];
    const float* pe           = (const float*)d_in[4];
    float* out                = (float*)d_out;

    pos_kernel<<<kB, 128>>>(mask);
    prep_w<<<720, 256>>>(wgt);
    prep_a<<<4096, 256>>>(pix);

    static bool attr_set = false;
    if (!attr_set) {
        cudaFuncSetAttribute(gemm_kernel,
                             cudaFuncAttributeMaxDynamicSharedMemorySize,
                             SMEM_SZ);
        attr_set = true;
    }
    dim3 grid(kM / BM, kD / BN);  // (169, 9)
    gemm_kernel<<<grid, 256, SMEM_SZ>>>(bias, pe, out);
}

// round 6
// speedup vs baseline: 3.7222x; 2.0655x over previous
#include <cuda_runtime.h>
#include <cuda_fp16.h>
#include <cstdint>

// ===========================================================================
// Idefics3VisionEmbeddings via single-term fp16 mma.sync (base sm_103 ISA).
//   out[m,n] = sum_k A[m,k]*W[n,k] + bias[n] + pos_emb[pos[m], n]
//   M=21632 (=169*128), N=1152 (=9*128), K=588 (pad 640)
// A, W rounded to fp16 (rn), fp32 accumulate. Norm-ratio error ~2e-4 < 1e-3.
// smem row pitch 144 B: 16B-aligned (ldmatrix/cp.async) and conflict-free.
// ===========================================================================

namespace {
constexpr int kNPS = 26, kPatch = 14, kB = 32, kC = 3, kHW = 364, kD = 1152;
constexpr int kP = kNPS * kNPS;           // 676
constexpr int kK = kC * kPatch * kPatch;  // 588
constexpr int kM = kB * kP;               // 21632
constexpr int kKpad = 640;

constexpr int BM = 128, BN = 128, BK = 64;
constexpr int NCHUNK = kKpad / BK;        // 10

// smem rows: 64 fp16 = 128 B, padded to 144 B (16B-aligned, conflict-free)
constexpr int ROWB = 144;
constexpr int ARR = 128 * ROWB;           // 18432 B
constexpr int STAGE = 2 * ARR;            // A + B = 36864 B
constexpr int NSTG = 3;
constexpr int SMEM_SZ = NSTG * STAGE;     // 110592
}  // namespace

// -------------------- device scratch (no cudaMalloc allowed) ---------------
__device__ __align__(256) __half g_Ah[(size_t)kM * kKpad];
__device__ __align__(256) __half g_Wh[(size_t)kD * kKpad];
__device__ int g_pos[kM];

// -------------------- helpers ----------------------------------------------
__device__ __forceinline__ uint32_t smem_u32(const void* p) {
    uint32_t a;
    asm("{ .reg .u64 t; cvta.to.shared.u64 t, %1; cvt.u32.u64 %0, t; }"
        : "=r"(a) : "l"(p));
    return a;
}
__device__ __forceinline__ void cp16(uint32_t dst, const void* src) {
    asm volatile("cp.async.cg.shared.global [%0], [%1], 16;"
                 :: "r"(dst), "l"(src) : "memory");
}
__device__ __forceinline__ void ldsm4(uint32_t* r, uint32_t addr) {
    asm volatile("ldmatrix.sync.aligned.m8n8.x4.shared.b16 {%0,%1,%2,%3}, [%4];"
                 : "=r"(r[0]), "=r"(r[1]), "=r"(r[2]), "=r"(r[3]) : "r"(addr));
}
__device__ __forceinline__ void mma16816(float* c, const uint32_t* a,
                                         const uint32_t* b) {
    asm volatile(
        "mma.sync.aligned.m16n8k16.row.col.f32.f16.f16.f32 "
        "{%0,%1,%2,%3}, {%4,%5,%6,%7}, {%8,%9}, {%0,%1,%2,%3};"
        : "+f"(c[0]), "+f"(c[1]), "+f"(c[2]), "+f"(c[3])
        : "r"(a[0]), "r"(a[1]), "r"(a[2]), "r"(a[3]), "r"(b[0]), "r"(b[1]));
}

// ---------------------------------------------------------------------------
// Position ids (exact fp32 replica of the reference). Mask dtype auto-detect:
// byte 1 nonzero => u8/bool layout (nb_w>=13 guarantees mask[0][0][1]==1).
// ---------------------------------------------------------------------------
__global__ void pos_kernel(const unsigned char* __restrict__ mraw) {
    const int b = blockIdx.x;
    const int t = threadIdx.x;
    __shared__ int s_bh[kNPS], s_bw[kNPS];
    __shared__ int s_nbh, s_nbw;

    const bool is_u8 = (mraw[1] != 0);
    auto mval = [&](int idx) -> int {
        return is_u8 ? (int)mraw[idx] : (int)mraw[4 * (size_t)idx];
    };
    const int base = b * kP;
    if (t == 0) {
        int nh = 0, nw = 0;
        for (int i = 0; i < kNPS; i++) nh += (mval(base + i * kNPS) != 0);
        for (int j = 0; j < kNPS; j++) nw += (mval(base + j) != 0);
        s_nbh = nh; s_nbw = nw;
    }
    __syncthreads();
    if (t < kNPS) {
        const float eps = 1.0f - 1e-6f;
        const float fh = ((float)t / (float)s_nbh) * eps;
        const float fw = ((float)t / (float)s_nbw) * eps;
        int ch = 0, cw = 0;
        #pragma unroll
        for (int j = 1; j < kNPS; j++) {
            const float bnd = (float)j / (float)kNPS;
            ch += (bnd <= fh) ? 1 : 0;
            cw += (bnd <= fw) ? 1 : 0;
        }
        s_bh[t] = ch; s_bw[t] = cw;
    }
    __syncthreads();
    for (int p = t; p < kP; p += blockDim.x) {
        const int ph = p / kNPS;
        const int pw = p - ph * kNPS;
        g_pos[base + p] = (mval(base + p) != 0) ? (s_bh[ph] * kNPS + s_bw[pw]) : 0;
    }
}

// ---------------------------------------------------------------------------
// Prep: im2col A -> fp16 [kM, kKpad]; W -> fp16 [kD, kKpad].
// ---------------------------------------------------------------------------
__global__ void prep_a(const float* __restrict__ pix) {
    const int total = kM * kKpad;
    for (int idx = blockIdx.x * blockDim.x + threadIdx.x; idx < total;
         idx += gridDim.x * blockDim.x) {
        const int m = idx / kKpad;
        const int k = idx - m * kKpad;
        float v = 0.f;
        if (k < kK) {
            const int b = m / kP;
            const int rem = m - b * kP;
            const int ph = rem / kNPS;
            const int pw = rem - ph * kNPS;
            const int c = k / (kPatch * kPatch);
            const int r = k - c * (kPatch * kPatch);
            const int ky = r / kPatch;
            const int kx = r - ky * kPatch;
            v = pix[(size_t)b * (kC * kHW * kHW) + (size_t)c * (kHW * kHW)
                    + (ph * kPatch + ky) * kHW + (pw * kPatch + kx)];
        }
        g_Ah[idx] = __float2half_rn(v);
    }
}

__global__ void prep_w(const float* __restrict__ wgt) {
    const int total = kD * kKpad;
    for (int idx = blockIdx.x * blockDim.x + threadIdx.x; idx < total;
         idx += gridDim.x * blockDim.x) {
        const int n = idx / kKpad;
        const int k = idx - n * kKpad;
        g_Wh[idx] = __float2half_rn((k < kK) ? wgt[(size_t)n * kK + k] : 0.f);
    }
}

// ---------------------------------------------------------------------------
// GEMM: 128x128 tile, BK=64, 3-stage cp.async, 8 warps (warp tile 32x64),
// 2 CTAs/SM.
// ---------------------------------------------------------------------------
__global__ void __launch_bounds__(256, 2)
gemm_kernel(const float* __restrict__ bias,
            const float* __restrict__ pe,
            float* __restrict__ out) {
    extern __shared__ char smem[];
    const uint32_t sbase = smem_u32(smem);
    const int tid = threadIdx.x;
    const int wid = tid >> 5;
    const int lane = tid & 31;

    const int m0 = blockIdx.x * BM;
    const int n0 = blockIdx.y * BN;

    const int warp_m = (wid & 3) * 32;   // 4 warps along M
    const int warp_n = (wid >> 2) * 64;  // 2 warps along N

    // loader: thread t -> row t>>1, four 16B chunks starting at (t&1)*4
    const int lrow = tid >> 1;
    const int lc0 = (tid & 1) * 4;
    const __half* gA = g_Ah + (size_t)(m0 + lrow) * kKpad;
    const __half* gB = g_Wh + (size_t)(n0 + lrow) * kKpad;

    auto load_chunk = [&](int j, int s) {
        const int k0 = j * BK;
        const uint32_t sb = sbase + s * STAGE + lrow * ROWB;
        #pragma unroll
        for (int q = 0; q < 4; q++) {
            const int c = lc0 + q;
            cp16(sb + c * 16,       gA + k0 + c * 8);
            cp16(sb + ARR + c * 16, gB + k0 + c * 8);
        }
        asm volatile("cp.async.commit_group;" ::: "memory");
    };

    // ldmatrix per-thread offsets
    const int sel = lane >> 3, li = lane & 7;
    const int aRow = (sel & 1) * 8 + li;      // +8 rows on sel bit0
    const int aC16 = (sel >> 1) * 16;         // +16B (k+8) on sel bit1
    const int bRow = (sel >> 1) * 8 + li;     // +8 n-rows on sel bit1
    const int bC16 = (sel & 1) * 16;          // +16B (k+8) on sel bit0

    float acc[2][8][4];
    #pragma unroll
    for (int i = 0; i < 2; i++)
        #pragma unroll
        for (int j = 0; j < 8; j++)
            #pragma unroll
            for (int q = 0; q < 4; q++) acc[i][j][q] = 0.f;

    load_chunk(0, 0);
    load_chunk(1, 1);

    #pragma unroll 1
    for (int j = 0; j < NCHUNK; j++) {
        const int s = j % 3;
        if (j < NCHUNK - 1)
            asm volatile("cp.async.wait_group 1;" ::: "memory");
        else
            asm volatile("cp.async.wait_group 0;" ::: "memory");
        __syncthreads();

        if (j + 2 < NCHUNK) load_chunk(j + 2, (j + 2) % 3);

        const uint32_t st = sbase + s * STAGE;
        const uint32_t aBase = st + (warp_m + aRow) * ROWB + aC16;
        const uint32_t bBase = st + ARR + (warp_n + bRow) * ROWB + bC16;

        #pragma unroll
        for (int ks = 0; ks < 4; ks++) {
            uint32_t af[2][4], bf[4][4];
            #pragma unroll
            for (int mt = 0; mt < 2; mt++)
                ldsm4(af[mt], aBase + mt * 16 * ROWB + ks * 32);
            #pragma unroll
            for (int bt = 0; bt < 4; bt++)
                ldsm4(bf[bt], bBase + bt * 16 * ROWB + ks * 32);
            #pragma unroll
            for (int mt = 0; mt < 2; mt++)
                #pragma unroll
                for (int nt = 0; nt < 8; nt++)
                    mma16816(acc[mt][nt], af[mt], &bf[nt >> 1][(nt & 1) * 2]);
        }
    }

    // ---------------- epilogue: + bias + pos_emb[pos[m]] --------------------
    const int r = lane >> 2, cg = lane & 3;
    #pragma unroll
    for (int mt = 0; mt < 2; mt++) {
        #pragma unroll
        for (int h = 0; h < 2; h++) {
            const int m = m0 + warp_m + mt * 16 + h * 8 + r;
            const float* per = pe + (size_t)g_pos[m] * kD;
            float* orow = out + (size_t)m * kD;
            #pragma unroll
            for (int nt = 0; nt < 8; nt++) {
                const int n = n0 + warp_n + nt * 8 + cg * 2;
                const float2 p = *reinterpret_cast<const float2*>(per + n);
                const float2 bv = *reinterpret_cast<const float2*>(bias + n);
                float2 v;
                v.x = acc[mt][nt][h * 2 + 0] + p.x + bv.x;
                v.y = acc[mt][nt][h * 2 + 1] + p.y + bv.y;
                *reinterpret_cast<float2*>(orow + n) = v;
            }
        }
    }
}

// ---------------------------------------------------------------------------
extern "C" void kernel_launch(void* const* d_in, const int* in_sizes, int n_in,
                              void* d_out, int out_size) {
    const float* pix          = (const float*)d_in[0];
    const unsigned char* mask = (const unsigned char*)d_in[1];
    const float* wgt          = (const float*)d_in[2];
    const float* bias         = (const float*)d_in[3];
    const float* pe           = (const float*)d_in[4];
    float* out                = (float*)d_out;

    pos_kernel<<<kB, 128>>>(mask);
    prep_w<<<720, 256>>>(wgt);
    prep_a<<<4096, 256>>>(pix);

    static bool attr_set = false;
    if (!attr_set) {
        cudaFuncSetAttribute(gemm_kernel,
                             cudaFuncAttributeMaxDynamicSharedMemorySize,
                             SMEM_SZ);
        attr_set = true;
    }
    dim3 grid(kM / BM, kD / BN);  // (169, 9)
    gemm_kernel<<<grid, 256, SMEM_SZ>>>(bias, pe, out);
}

// round 7
// speedup vs baseline: 4.0805x; 1.0962x over previous
#include <cuda_runtime.h>
#include <cuda_fp16.h>
#include <cstdint>

// ===========================================================================
// Idefics3VisionEmbeddings via single-term fp16 mma.sync (base sm_103 ISA).
//   out[m,n] = sum_k A[m,k]*W[n,k] + bias[n] + pos_emb[pos[m], n]
//   M=21632 (pad 21760 = 85*256), N=1152 (=9*128), K=588 (pad 640)
// fp16 inputs (rn), fp32 accumulate. Norm-ratio error ~3e-4 < 1e-3.
// Block tile 256x128, warp tile 64x64 (8 warps), BK=64, 3-stage cp.async.
// ===========================================================================

namespace {
constexpr int kNPS = 26, kPatch = 14, kB = 32, kC = 3, kHW = 364, kD = 1152;
constexpr int kP = kNPS * kNPS;           // 676
constexpr int kK = kC * kPatch * kPatch;  // 588
constexpr int kM = kB * kP;               // 21632
constexpr int kKpad = 640;
constexpr int kMpad = 21760;              // 85 * 256

constexpr int BM = 256, BN = 128, BK = 64;
constexpr int NCHUNK = kKpad / BK;        // 10

// smem rows: 64 fp16 = 128 B, padded to 144 B (16B-aligned, conflict-free)
constexpr int ROWB = 144;
constexpr int ARR_A = BM * ROWB;          // 36864 B
constexpr int ARR_B = BN * ROWB;          // 18432 B
constexpr int STAGE = ARR_A + ARR_B;      // 55296 B
constexpr int NSTG = 3;
constexpr int SMEM_SZ = NSTG * STAGE;     // 165888
}  // namespace

// -------------------- device scratch (no cudaMalloc allowed) ---------------
__device__ __align__(256) __half g_Ah[(size_t)kMpad * kKpad];
__device__ __align__(256) __half g_Wh[(size_t)kD * kKpad];
__device__ int g_pos[kM];

// -------------------- helpers ----------------------------------------------
__device__ __forceinline__ uint32_t smem_u32(const void* p) {
    uint32_t a;
    asm("{ .reg .u64 t; cvta.to.shared.u64 t, %1; cvt.u32.u64 %0, t; }"
        : "=r"(a) : "l"(p));
    return a;
}
__device__ __forceinline__ void cp16(uint32_t dst, const void* src) {
    asm volatile("cp.async.cg.shared.global [%0], [%1], 16;"
                 :: "r"(dst), "l"(src) : "memory");
}
__device__ __forceinline__ void ldsm4(uint32_t* r, uint32_t addr) {
    asm volatile("ldmatrix.sync.aligned.m8n8.x4.shared.b16 {%0,%1,%2,%3}, [%4];"
                 : "=r"(r[0]), "=r"(r[1]), "=r"(r[2]), "=r"(r[3]) : "r"(addr));
}
__device__ __forceinline__ void mma16816(float* c, const uint32_t* a,
                                         const uint32_t* b) {
    asm volatile(
        "mma.sync.aligned.m16n8k16.row.col.f32.f16.f16.f32 "
        "{%0,%1,%2,%3}, {%4,%5,%6,%7}, {%8,%9}, {%0,%1,%2,%3};"
        : "+f"(c[0]), "+f"(c[1]), "+f"(c[2]), "+f"(c[3])
        : "r"(a[0]), "r"(a[1]), "r"(a[2]), "r"(a[3]), "r"(b[0]), "r"(b[1]));
}

// ---------------------------------------------------------------------------
// Position ids (exact fp32 replica of the reference). Mask dtype auto-detect:
// byte 1 nonzero => u8/bool layout (nb_w>=13 guarantees mask[0][0][1]==1).
// ---------------------------------------------------------------------------
__global__ void pos_kernel(const unsigned char* __restrict__ mraw) {
    const int b = blockIdx.x;
    const int t = threadIdx.x;
    __shared__ int s_bh[kNPS], s_bw[kNPS];
    __shared__ int s_nbh, s_nbw;

    const bool is_u8 = (mraw[1] != 0);
    auto mval = [&](int idx) -> int {
        return is_u8 ? (int)mraw[idx] : (int)mraw[4 * (size_t)idx];
    };
    const int base = b * kP;
    if (t == 0) {
        int nh = 0, nw = 0;
        for (int i = 0; i < kNPS; i++) nh += (mval(base + i * kNPS) != 0);
        for (int j = 0; j < kNPS; j++) nw += (mval(base + j) != 0);
        s_nbh = nh; s_nbw = nw;
    }
    __syncthreads();
    if (t < kNPS) {
        const float eps = 1.0f - 1e-6f;
        const float fh = ((float)t / (float)s_nbh) * eps;
        const float fw = ((float)t / (float)s_nbw) * eps;
        int ch = 0, cw = 0;
        #pragma unroll
        for (int j = 1; j < kNPS; j++) {
            const float bnd = (float)j / (float)kNPS;
            ch += (bnd <= fh) ? 1 : 0;
            cw += (bnd <= fw) ? 1 : 0;
        }
        s_bh[t] = ch; s_bw[t] = cw;
    }
    __syncthreads();
    for (int p = t; p < kP; p += blockDim.x) {
        const int ph = p / kNPS;
        const int pw = p - ph * kNPS;
        g_pos[base + p] = (mval(base + p) != 0) ? (s_bh[ph] * kNPS + s_bw[pw]) : 0;
    }
}

// ---------------------------------------------------------------------------
// Prep: im2col A -> fp16 [kMpad, kKpad]; W -> fp16 [kD, kKpad].
// ---------------------------------------------------------------------------
__global__ void prep_a(const float* __restrict__ pix) {
    const int total = kMpad * kKpad;
    for (int idx = blockIdx.x * blockDim.x + threadIdx.x; idx < total;
         idx += gridDim.x * blockDim.x) {
        const int m = idx / kKpad;
        const int k = idx - m * kKpad;
        float v = 0.f;
        if (m < kM && k < kK) {
            const int b = m / kP;
            const int rem = m - b * kP;
            const int ph = rem / kNPS;
            const int pw = rem - ph * kNPS;
            const int c = k / (kPatch * kPatch);
            const int r = k - c * (kPatch * kPatch);
            const int ky = r / kPatch;
            const int kx = r - ky * kPatch;
            v = pix[(size_t)b * (kC * kHW * kHW) + (size_t)c * (kHW * kHW)
                    + (ph * kPatch + ky) * kHW + (pw * kPatch + kx)];
        }
        g_Ah[idx] = __float2half_rn(v);
    }
}

__global__ void prep_w(const float* __restrict__ wgt) {
    const int total = kD * kKpad;
    for (int idx = blockIdx.x * blockDim.x + threadIdx.x; idx < total;
         idx += gridDim.x * blockDim.x) {
        const int n = idx / kKpad;
        const int k = idx - n * kKpad;
        g_Wh[idx] = __float2half_rn((k < kK) ? wgt[(size_t)n * kK + k] : 0.f);
    }
}

// ---------------------------------------------------------------------------
// GEMM: 256x128 tile, warp tile 64x64, BK=64, 3-stage cp.async, 8 warps.
// ---------------------------------------------------------------------------
__global__ void __launch_bounds__(256, 1)
gemm_kernel(const float* __restrict__ bias,
            const float* __restrict__ pe,
            float* __restrict__ out) {
    extern __shared__ char smem[];
    const uint32_t sbase = smem_u32(smem);
    const int tid = threadIdx.x;
    const int wid = tid >> 5;
    const int lane = tid & 31;

    const int m0 = blockIdx.x * BM;
    const int n0 = blockIdx.y * BN;

    const int warp_m = (wid & 3) * 64;   // 4 warps along M
    const int warp_n = (wid >> 2) * 64;  // 2 warps along N

    auto load_chunk = [&](int j, int s) {
        const int k0 = j * BK;
        const uint32_t sb = sbase + s * STAGE;
        // A: 256 rows x 8 chunks of 16B = 2048 transfers (8 per thread)
        #pragma unroll
        for (int i = 0; i < 8; i++) {
            const int idx = tid + 256 * i;
            const int row = idx >> 3, c = idx & 7;
            cp16(sb + row * ROWB + c * 16,
                 g_Ah + (size_t)(m0 + row) * kKpad + k0 + c * 8);
        }
        // B: 128 rows x 8 chunks = 1024 transfers (4 per thread)
        #pragma unroll
        for (int i = 0; i < 4; i++) {
            const int idx = tid + 256 * i;
            const int row = idx >> 3, c = idx & 7;
            cp16(sb + ARR_A + row * ROWB + c * 16,
                 g_Wh + (size_t)(n0 + row) * kKpad + k0 + c * 8);
        }
        asm volatile("cp.async.commit_group;" ::: "memory");
    };

    // ldmatrix per-thread offsets
    const int sel = lane >> 3, li = lane & 7;
    const int aRow = (sel & 1) * 8 + li;      // +8 rows on sel bit0
    const int aC16 = (sel >> 1) * 16;         // +16B (k+8) on sel bit1
    const int bRow = (sel >> 1) * 8 + li;     // +8 n-rows on sel bit1
    const int bC16 = (sel & 1) * 16;          // +16B (k+8) on sel bit0

    float acc[4][8][4];
    #pragma unroll
    for (int i = 0; i < 4; i++)
        #pragma unroll
        for (int j = 0; j < 8; j++)
            #pragma unroll
            for (int q = 0; q < 4; q++) acc[i][j][q] = 0.f;

    load_chunk(0, 0);
    load_chunk(1, 1);

    #pragma unroll 1
    for (int j = 0; j < NCHUNK; j++) {
        const int s = j % 3;
        if (j < NCHUNK - 1)
            asm volatile("cp.async.wait_group 1;" ::: "memory");
        else
            asm volatile("cp.async.wait_group 0;" ::: "memory");
        __syncthreads();

        if (j + 2 < NCHUNK) load_chunk(j + 2, (j + 2) % 3);

        const uint32_t st = sbase + s * STAGE;
        const uint32_t aBase = st + (warp_m + aRow) * ROWB + aC16;
        const uint32_t bBase = st + ARR_A + (warp_n + bRow) * ROWB + bC16;

        #pragma unroll
        for (int ks = 0; ks < 4; ks++) {
            uint32_t af[4][4], bf[4][4];
            #pragma unroll
            for (int mt = 0; mt < 4; mt++)
                ldsm4(af[mt], aBase + mt * 16 * ROWB + ks * 32);
            #pragma unroll
            for (int bt = 0; bt < 4; bt++)
                ldsm4(bf[bt], bBase + bt * 16 * ROWB + ks * 32);
            #pragma unroll
            for (int mt = 0; mt < 4; mt++)
                #pragma unroll
                for (int nt = 0; nt < 8; nt++)
                    mma16816(acc[mt][nt], af[mt], &bf[nt >> 1][(nt & 1) * 2]);
        }
    }

    // ---------------- epilogue: + bias + pos_emb[pos[m]] --------------------
    const int r = lane >> 2, cg = lane & 3;
    #pragma unroll
    for (int mt = 0; mt < 4; mt++) {
        #pragma unroll
        for (int h = 0; h < 2; h++) {
            const int m = m0 + warp_m + mt * 16 + h * 8 + r;
            if (m >= kM) continue;
            const float* per = pe + (size_t)g_pos[m] * kD;
            float* orow = out + (size_t)m * kD;
            #pragma unroll
            for (int nt = 0; nt < 8; nt++) {
                const int n = n0 + warp_n + nt * 8 + cg * 2;
                const float2 p = *reinterpret_cast<const float2*>(per + n);
                const float2 bv = *reinterpret_cast<const float2*>(bias + n);
                float2 v;
                v.x = acc[mt][nt][h * 2 + 0] + p.x + bv.x;
                v.y = acc[mt][nt][h * 2 + 1] + p.y + bv.y;
                *reinterpret_cast<float2*>(orow + n) = v;
            }
        }
    }
}

// ---------------------------------------------------------------------------
extern "C" void kernel_launch(void* const* d_in, const int* in_sizes, int n_in,
                              void* d_out, int out_size) {
    const float* pix          = (const float*)d_in[0];
    const unsigned char* mask = (const unsigned char*)d_in[1];
    const float* wgt          = (const float*)d_in[2];
    const float* bias         = (const float*)d_in[3];
    const float* pe           = (const float*)d_in[4];
    float* out                = (float*)d_out;

    pos_kernel<<<kB, 128>>>(mask);
    prep_w<<<720, 256>>>(wgt);
    prep_a<<<4096, 256>>>(pix);

    static bool attr_set = false;
    if (!attr_set) {
        cudaFuncSetAttribute(gemm_kernel,
                             cudaFuncAttributeMaxDynamicSharedMemorySize,
                             SMEM_SZ);
        attr_set = true;
    }
    dim3 grid(kMpad / BM, kD / BN);  // (85, 9)
    gemm_kernel<<<grid, 256, SMEM_SZ>>>(bias, pe, out);
}

// round 8
// speedup vs baseline: 4.5383x; 1.1122x over previous
#include <cuda_runtime.h>
#include <cuda_fp16.h>
#include <cstdint>

// ===========================================================================
// Idefics3VisionEmbeddings via single-term fp16 mma.sync (base sm_103 ISA).
//   out[m,n] = sum_k A[m,k]*W[n,k] + bias[n] + pos_emb[pos[m], n]
//   M=21632 (=169*128 exact), N=1152 (=6*192), K=588 (pad 640)
// fp16 inputs (rn), fp32 accumulate. Norm-ratio error ~3e-4 < 1e-3.
// Block tile 128x192, warp tile 64x48 (8 warps), BK=64, 4-stage cp.async.
// Grid 169x6 = 1014 CTAs -> 6.85 waves (2% tail vs 16% at BM=256).
// ===========================================================================

namespace {
constexpr int kNPS = 26, kPatch = 14, kB = 32, kC = 3, kHW = 364, kD = 1152;
constexpr int kP = kNPS * kNPS;           // 676
constexpr int kK = kC * kPatch * kPatch;  // 588
constexpr int kM = kB * kP;               // 21632
constexpr int kKpad = 640;

constexpr int BM = 128, BN = 192, BK = 64;
constexpr int NCHUNK = kKpad / BK;        // 10

// smem rows: 64 fp16 = 128 B, padded to 144 B (16B-aligned; conflict-free
// for both ldmatrix octets and cp.async 16B stores)
constexpr int ROWB = 144;
constexpr int ARR_A = BM * ROWB;          // 18432 B
constexpr int ARR_B = BN * ROWB;          // 27648 B
constexpr int STAGE = ARR_A + ARR_B;      // 46080 B
constexpr int NSTG = 4;
constexpr int SMEM_SZ = NSTG * STAGE;     // 184320
}  // namespace

// -------------------- device scratch (no cudaMalloc allowed) ---------------
__device__ __align__(256) __half g_Ah[(size_t)kM * kKpad];
__device__ __align__(256) __half g_Wh[(size_t)kD * kKpad];
__device__ int g_pos[kM];

// -------------------- helpers ----------------------------------------------
__device__ __forceinline__ uint32_t smem_u32(const void* p) {
    uint32_t a;
    asm("{ .reg .u64 t; cvta.to.shared.u64 t, %1; cvt.u32.u64 %0, t; }"
        : "=r"(a) : "l"(p));
    return a;
}
__device__ __forceinline__ void cp16(uint32_t dst, const void* src) {
    asm volatile("cp.async.cg.shared.global [%0], [%1], 16;"
                 :: "r"(dst), "l"(src) : "memory");
}
__device__ __forceinline__ void ldsm4(uint32_t* r, uint32_t addr) {
    asm volatile("ldmatrix.sync.aligned.m8n8.x4.shared.b16 {%0,%1,%2,%3}, [%4];"
                 : "=r"(r[0]), "=r"(r[1]), "=r"(r[2]), "=r"(r[3]) : "r"(addr));
}
__device__ __forceinline__ void mma16816(float* c, const uint32_t* a,
                                         const uint32_t* b) {
    asm volatile(
        "mma.sync.aligned.m16n8k16.row.col.f32.f16.f16.f32 "
        "{%0,%1,%2,%3}, {%4,%5,%6,%7}, {%8,%9}, {%0,%1,%2,%3};"
        : "+f"(c[0]), "+f"(c[1]), "+f"(c[2]), "+f"(c[3])
        : "r"(a[0]), "r"(a[1]), "r"(a[2]), "r"(a[3]), "r"(b[0]), "r"(b[1]));
}

// ---------------------------------------------------------------------------
// Position ids (exact fp32 replica of the reference). Mask dtype auto-detect:
// byte 1 nonzero => u8/bool layout (nb_w>=13 guarantees mask[0][0][1]==1).
// ---------------------------------------------------------------------------
__global__ void pos_kernel(const unsigned char* __restrict__ mraw) {
    const int b = blockIdx.x;
    const int t = threadIdx.x;
    __shared__ int s_bh[kNPS], s_bw[kNPS];
    __shared__ int s_nbh, s_nbw;

    const bool is_u8 = (mraw[1] != 0);
    auto mval = [&](int idx) -> int {
        return is_u8 ? (int)mraw[idx] : (int)mraw[4 * (size_t)idx];
    };
    const int base = b * kP;
    if (t == 0) {
        int nh = 0, nw = 0;
        for (int i = 0; i < kNPS; i++) nh += (mval(base + i * kNPS) != 0);
        for (int j = 0; j < kNPS; j++) nw += (mval(base + j) != 0);
        s_nbh = nh; s_nbw = nw;
    }
    __syncthreads();
    if (t < kNPS) {
        const float eps = 1.0f - 1e-6f;
        const float fh = ((float)t / (float)s_nbh) * eps;
        const float fw = ((float)t / (float)s_nbw) * eps;
        int ch = 0, cw = 0;
        #pragma unroll
        for (int j = 1; j < kNPS; j++) {
            const float bnd = (float)j / (float)kNPS;
            ch += (bnd <= fh) ? 1 : 0;
            cw += (bnd <= fw) ? 1 : 0;
        }
        s_bh[t] = ch; s_bw[t] = cw;
    }
    __syncthreads();
    for (int p = t; p < kP; p += blockDim.x) {
        const int ph = p / kNPS;
        const int pw = p - ph * kNPS;
        g_pos[base + p] = (mval(base + p) != 0) ? (s_bh[ph] * kNPS + s_bw[pw]) : 0;
    }
}

// ---------------------------------------------------------------------------
// Prep: im2col A -> fp16 [kM, kKpad] (half2-vectorized: patch rows are 14
// long and start at even offsets, so k-pairs never straddle a pixel row).
// ---------------------------------------------------------------------------
__global__ void prep_a(const float* __restrict__ pix) {
    const int total = kM * (kKpad / 2);
    for (int idx = blockIdx.x * blockDim.x + threadIdx.x; idx < total;
         idx += gridDim.x * blockDim.x) {
        const int m = idx / (kKpad / 2);
        const int k2 = idx - m * (kKpad / 2);
        const int k = k2 * 2;
        __half2 hv = __float2half2_rn(0.f);
        if (k < kK) {
            const int b = m / kP;
            const int rem = m - b * kP;
            const int ph = rem / kNPS;
            const int pw = rem - ph * kNPS;
            const int c = k / (kPatch * kPatch);
            const int r = k - c * (kPatch * kPatch);
            const int ky = r / kPatch;
            const int kx = r - ky * kPatch;
            const float2 v = *reinterpret_cast<const float2*>(
                pix + (size_t)b * (kC * kHW * kHW) + (size_t)c * (kHW * kHW)
                + (ph * kPatch + ky) * kHW + (pw * kPatch + kx));
            hv = __floats2half2_rn(v.x, v.y);
        }
        *reinterpret_cast<__half2*>(g_Ah + (size_t)m * kKpad + k) = hv;
    }
}

__global__ void prep_w(const float* __restrict__ wgt) {
    const int total = kD * kKpad;
    for (int idx = blockIdx.x * blockDim.x + threadIdx.x; idx < total;
         idx += gridDim.x * blockDim.x) {
        const int n = idx / kKpad;
        const int k = idx - n * kKpad;
        g_Wh[idx] = __float2half_rn((k < kK) ? wgt[(size_t)n * kK + k] : 0.f);
    }
}

// ---------------------------------------------------------------------------
// GEMM: 128x192 tile, warp tile 64x48, BK=64, 4-stage cp.async, 8 warps.
// ---------------------------------------------------------------------------
__global__ void __launch_bounds__(256, 1)
gemm_kernel(const float* __restrict__ bias,
            const float* __restrict__ pe,
            float* __restrict__ out) {
    extern __shared__ char smem[];
    const uint32_t sbase = smem_u32(smem);
    const int tid = threadIdx.x;
    const int wid = tid >> 5;
    const int lane = tid & 31;

    const int m0 = blockIdx.x * BM;
    const int n0 = blockIdx.y * BN;

    const int warp_m = (wid & 1) * 64;   // 2 warps along M
    const int warp_n = (wid >> 1) * 48;  // 4 warps along N

    auto load_chunk = [&](int j, int s) {
        const int k0 = j * BK;
        const uint32_t sb = sbase + s * STAGE;
        // A: 128 rows x 8 chunks of 16B = 1024 transfers (4 per thread)
        #pragma unroll
        for (int i = 0; i < 4; i++) {
            const int idx = tid + 256 * i;
            const int row = idx >> 3, c = idx & 7;
            cp16(sb + row * ROWB + c * 16,
                 g_Ah + (size_t)(m0 + row) * kKpad + k0 + c * 8);
        }
        // B: 192 rows x 8 chunks = 1536 transfers (6 per thread)
        #pragma unroll
        for (int i = 0; i < 6; i++) {
            const int idx = tid + 256 * i;
            const int row = idx >> 3, c = idx & 7;
            cp16(sb + ARR_A + row * ROWB + c * 16,
                 g_Wh + (size_t)(n0 + row) * kKpad + k0 + c * 8);
        }
        asm volatile("cp.async.commit_group;" ::: "memory");
    };

    // ldmatrix per-thread offsets
    const int sel = lane >> 3, li = lane & 7;
    const int aRow = (sel & 1) * 8 + li;      // +8 rows on sel bit0
    const int aC16 = (sel >> 1) * 16;         // +16B (k+8) on sel bit1
    const int bRow = (sel >> 1) * 8 + li;     // +8 n-rows on sel bit1
    const int bC16 = (sel & 1) * 16;          // +16B (k+8) on sel bit0

    float acc[4][6][4];
    #pragma unroll
    for (int i = 0; i < 4; i++)
        #pragma unroll
        for (int j = 0; j < 6; j++)
            #pragma unroll
            for (int q = 0; q < 4; q++) acc[i][j][q] = 0.f;

    load_chunk(0, 0);
    load_chunk(1, 1);
    load_chunk(2, 2);

    #pragma unroll 1
    for (int j = 0; j < NCHUNK; j++) {
        const int s = j & 3;
        asm volatile("cp.async.wait_group 2;" ::: "memory");
        __syncthreads();

        if (j + 3 < NCHUNK) {
            load_chunk(j + 3, (j + 3) & 3);
        } else {
            asm volatile("cp.async.commit_group;" ::: "memory");  // keep counts uniform
        }

        const uint32_t st = sbase + s * STAGE;
        const uint32_t aBase = st + (warp_m + aRow) * ROWB + aC16;
        const uint32_t bBase = st + ARR_A + (warp_n + bRow) * ROWB + bC16;

        #pragma unroll
        for (int ks = 0; ks < 4; ks++) {
            uint32_t af[4][4], bf[3][4];
            #pragma unroll
            for (int mt = 0; mt < 4; mt++)
                ldsm4(af[mt], aBase + mt * 16 * ROWB + ks * 32);
            #pragma unroll
            for (int bt = 0; bt < 3; bt++)
                ldsm4(bf[bt], bBase + bt * 16 * ROWB + ks * 32);
            #pragma unroll
            for (int mt = 0; mt < 4; mt++)
                #pragma unroll
                for (int nt = 0; nt < 6; nt++)
                    mma16816(acc[mt][nt], af[mt], &bf[nt >> 1][(nt & 1) * 2]);
        }
    }

    // ---------------- epilogue: + bias + pos_emb[pos[m]] --------------------
    const int r = lane >> 2, cg = lane & 3;
    #pragma unroll
    for (int mt = 0; mt < 4; mt++) {
        #pragma unroll
        for (int h = 0; h < 2; h++) {
            const int m = m0 + warp_m + mt * 16 + h * 8 + r;
            const float* per = pe + (size_t)g_pos[m] * kD;
            float* orow = out + (size_t)m * kD;
            #pragma unroll
            for (int nt = 0; nt < 6; nt++) {
                const int n = n0 + warp_n + nt * 8 + cg * 2;
                const float2 p = *reinterpret_cast<const float2*>(per + n);
                const float2 bv = *reinterpret_cast<const float2*>(bias + n);
                float2 v;
                v.x = acc[mt][nt][h * 2 + 0] + p.x + bv.x;
                v.y = acc[mt][nt][h * 2 + 1] + p.y + bv.y;
                *reinterpret_cast<float2*>(orow + n) = v;
            }
        }
    }
}

// ---------------------------------------------------------------------------
extern "C" void kernel_launch(void* const* d_in, const int* in_sizes, int n_in,
                              void* d_out, int out_size) {
    const float* pix          = (const float*)d_in[0];
    const unsigned char* mask = (const unsigned char*)d_in[1];
    const float* wgt          = (const float*)d_in[2];
    const float* bias         = (const float*)d_in[3];
    const float* pe           = (const float*)d_in[4];
    float* out                = (float*)d_out;

    pos_kernel<<<kB, 128>>>(mask);
    prep_w<<<720, 256>>>(wgt);
    prep_a<<<2048, 256>>>(pix);

    static bool attr_set = false;
    if (!attr_set) {
        cudaFuncSetAttribute(gemm_kernel,
                             cudaFuncAttributeMaxDynamicSharedMemorySize,
                             SMEM_SZ);
        attr_set = true;
    }
    dim3 grid(kM / BM, kD / BN);  // (169, 6)
    gemm_kernel<<<grid, 256, SMEM_SZ>>>(bias, pe, out);
}

// round 10
// speedup vs baseline: 4.6157x; 1.0170x over previous
#include <cuda_runtime.h>
#include <cuda_fp16.h>
#include <cstdint>

// ===========================================================================
// Idefics3VisionEmbeddings via single-term fp16 mma.sync (base sm_103 ISA).
//   out[m,n] = sum_k A[m,k]*W[n,k] + bias[n] + pos_emb[pos[m], n]
//   M=21632 (=169*128 exact), N=1152 (=6*192), K=588 (pad 592)
// fp16 inputs (rn), fp32 accumulate. Norm-ratio error ~3e-4 < 1e-3.
// Block tile 128x192, warp tile 64x48 (8 warps), BK=64 (last chunk 16),
// 4-stage ring with mbarrier full/empty pairs (no __syncthreads in loop).
// Producer arrives use cp.async.mbarrier.arrive.NOINC (default form is
// count-neutral and deadlocks -- R8 post-mortem).
// ===========================================================================

namespace {
constexpr int kNPS = 26, kPatch = 14, kB = 32, kC = 3, kHW = 364, kD = 1152;
constexpr int kP = kNPS * kNPS;           // 676
constexpr int kK = kC * kPatch * kPatch;  // 588
constexpr int kM = kB * kP;               // 21632
constexpr int kKpad = 592;                // 37 * 16

constexpr int BM = 128, BN = 192, BK = 64;
constexpr int NCHUNK = 10;                // 9 full (64) + 1 partial (16)

// smem rows: 64 fp16 = 128 B, padded to 144 B (16B-aligned; conflict-free)
constexpr int ROWB = 144;
constexpr int ARR_A = BM * ROWB;          // 18432 B
constexpr int ARR_B = BN * ROWB;          // 27648 B
constexpr int STAGE = ARR_A + ARR_B;      // 46080 B
constexpr int NSTG = 4;
constexpr int BARS = 64;                  // barrier block (full[4], empty[4])
constexpr int SMEM_SZ = BARS + NSTG * STAGE;
}  // namespace

// -------------------- device scratch (no cudaMalloc allowed) ---------------
__device__ __align__(256) __half g_Ah[(size_t)kM * kKpad];
__device__ __align__(256) __half g_Wh[(size_t)kD * kKpad];
__device__ int g_pos[kM];

// -------------------- helpers ----------------------------------------------
__device__ __forceinline__ uint32_t smem_u32(const void* p) {
    uint32_t a;
    asm("{ .reg .u64 t; cvta.to.shared.u64 t, %1; cvt.u32.u64 %0, t; }"
        : "=r"(a) : "l"(p));
    return a;
}
__device__ __forceinline__ void cp16(uint32_t dst, const void* src) {
    asm volatile("cp.async.cg.shared.global [%0], [%1], 16;"
                 :: "r"(dst), "l"(src) : "memory");
}
__device__ __forceinline__ void cp_mbar_arrive_noinc(uint32_t bar) {
    asm volatile("cp.async.mbarrier.arrive.noinc.shared::cta.b64 [%0];"
                 :: "r"(bar) : "memory");
}
__device__ __forceinline__ void mbar_init(uint32_t a, uint32_t cnt) {
    asm volatile("mbarrier.init.shared.b64 [%0], %1;" :: "r"(a), "r"(cnt) : "memory");
}
__device__ __forceinline__ void mbar_arrive(uint32_t a) {
    asm volatile("mbarrier.arrive.shared.b64 _, [%0];" :: "r"(a) : "memory");
}
__device__ __forceinline__ void mbar_wait(uint32_t a, uint32_t parity) {
    asm volatile(
        "{\n .reg .pred P;\n"
        "WL_%=:\n"
        " mbarrier.try_wait.parity.shared.b64 P, [%0], %1, 0x989680;\n"
        " @P bra WD_%=;\n"
        " bra WL_%=;\n"
        "WD_%=:\n}" :: "r"(a), "r"(parity) : "memory");
}
__device__ __forceinline__ void ldsm4(uint32_t* r, uint32_t addr) {
    asm volatile("ldmatrix.sync.aligned.m8n8.x4.shared.b16 {%0,%1,%2,%3}, [%4];"
                 : "=r"(r[0]), "=r"(r[1]), "=r"(r[2]), "=r"(r[3]) : "r"(addr));
}
__device__ __forceinline__ void mma16816(float* c, const uint32_t* a,
                                         const uint32_t* b) {
    asm volatile(
        "mma.sync.aligned.m16n8k16.row.col.f32.f16.f16.f32 "
        "{%0,%1,%2,%3}, {%4,%5,%6,%7}, {%8,%9}, {%0,%1,%2,%3};"
        : "+f"(c[0]), "+f"(c[1]), "+f"(c[2]), "+f"(c[3])
        : "r"(a[0]), "r"(a[1]), "r"(a[2]), "r"(a[3]), "r"(b[0]), "r"(b[1]));
}

// ---------------------------------------------------------------------------
// Position ids (exact fp32 replica of the reference). Mask dtype auto-detect:
// byte 1 nonzero => u8/bool layout (nb_w>=13 guarantees mask[0][0][1]==1).
// ---------------------------------------------------------------------------
__global__ void pos_kernel(const unsigned char* __restrict__ mraw) {
    const int b = blockIdx.x;
    const int t = threadIdx.x;
    __shared__ int s_bh[kNPS], s_bw[kNPS];
    __shared__ int s_nbh, s_nbw;

    const bool is_u8 = (mraw[1] != 0);
    auto mval = [&](int idx) -> int {
        return is_u8 ? (int)mraw[idx] : (int)mraw[4 * (size_t)idx];
    };
    const int base = b * kP;
    if (t == 0) {
        int nh = 0, nw = 0;
        for (int i = 0; i < kNPS; i++) nh += (mval(base + i * kNPS) != 0);
        for (int j = 0; j < kNPS; j++) nw += (mval(base + j) != 0);
        s_nbh = nh; s_nbw = nw;
    }
    __syncthreads();
    if (t < kNPS) {
        const float eps = 1.0f - 1e-6f;
        const float fh = ((float)t / (float)s_nbh) * eps;
        const float fw = ((float)t / (float)s_nbw) * eps;
        int ch = 0, cw = 0;
        #pragma unroll
        for (int j = 1; j < kNPS; j++) {
            const float bnd = (float)j / (float)kNPS;
            ch += (bnd <= fh) ? 1 : 0;
            cw += (bnd <= fw) ? 1 : 0;
        }
        s_bh[t] = ch; s_bw[t] = cw;
    }
    __syncthreads();
    for (int p = t; p < kP; p += blockDim.x) {
        const int ph = p / kNPS;
        const int pw = p - ph * kNPS;
        g_pos[base + p] = (mval(base + p) != 0) ? (s_bh[ph] * kNPS + s_bw[pw]) : 0;
    }
}

// ---------------------------------------------------------------------------
// Prep A: one block per (b, ph) strip. Reads contiguous 364-float pixel rows
// (perfectly coalesced), writes im2col fp16 rows for the 26 patches of the
// strip. half2 pairs never straddle a patch row (14 long, even offsets).
// ---------------------------------------------------------------------------
__global__ void prep_a(const float* __restrict__ pix) {
    const int b = blockIdx.x, ph = blockIdx.y;
    const float* src = pix + (size_t)b * (kC * kHW * kHW)
                       + (size_t)(ph * kPatch) * kHW;
    const int mbase = b * kP + ph * kNPS;
    constexpr int TOT = kC * kPatch * (kHW / 2);  // 7644 half2 elements
    for (int e = threadIdx.x; e < TOT; e += blockDim.x) {
        const int rowid = e / (kHW / 2);          // c*14 + ky
        const int x2 = e - rowid * (kHW / 2);
        const int c = rowid / kPatch;
        const int ky = rowid - c * kPatch;
        const int x = x2 * 2;
        const int pw = x / kPatch;
        const int kx = x - pw * kPatch;
        const float2 v = *reinterpret_cast<const float2*>(
            src + (size_t)c * (kHW * kHW) + ky * kHW + x);
        const int m = mbase + pw;
        const int k = c * (kPatch * kPatch) + ky * kPatch + kx;
        *reinterpret_cast<__half2*>(g_Ah + (size_t)m * kKpad + k) =
            __floats2half2_rn(v.x, v.y);
    }
}

// Zero the K padding [588, 592) of g_Ah.
__global__ void prep_pad() {
    const int total = kM * 2;  // two half2 per row
    for (int idx = blockIdx.x * blockDim.x + threadIdx.x; idx < total;
         idx += gridDim.x * blockDim.x) {
        const int m = idx >> 1;
        const int k = kK + (idx & 1) * 2;
        *reinterpret_cast<__half2*>(g_Ah + (size_t)m * kKpad + k) =
            __float2half2_rn(0.f);
    }
}

__global__ void prep_w(const float* __restrict__ wgt) {
    const int total = kD * kKpad;
    for (int idx = blockIdx.x * blockDim.x + threadIdx.x; idx < total;
         idx += gridDim.x * blockDim.x) {
        const int n = idx / kKpad;
        const int k = idx - n * kKpad;
        g_Wh[idx] = __float2half_rn((k < kK) ? wgt[(size_t)n * kK + k] : 0.f);
    }
}

// ---------------------------------------------------------------------------
// GEMM: 128x192 tile, warp tile 64x48, 4-stage mbarrier ring, 8 warps.
// ---------------------------------------------------------------------------
__global__ void __launch_bounds__(256, 1)
gemm_kernel(const float* __restrict__ bias,
            const float* __restrict__ pe,
            float* __restrict__ out) {
    extern __shared__ char smem[];
    const uint32_t sbase = smem_u32(smem);
    const uint32_t dbase = sbase + BARS;     // data stages
    const int tid = threadIdx.x;
    const int wid = tid >> 5;
    const int lane = tid & 31;

    const int m0 = blockIdx.x * BM;
    const int n0 = blockIdx.y * BN;

    const int warp_m = (wid & 1) * 64;   // 2 warps along M
    const int warp_n = (wid >> 1) * 48;  // 4 warps along N

    // full[s] at sbase + 8s, empty[s] at sbase + 32 + 8s; count = 256 each.
    if (tid == 0) {
        #pragma unroll
        for (int s = 0; s < NSTG; s++) {
            mbar_init(sbase + 8 * s, 256);
            mbar_init(sbase + 32 + 8 * s, 256);
        }
    }
    __syncthreads();

    // producer: issue this thread's cp.asyncs for chunk j into stage s,
    // then arrive full[s] with .noinc once this thread's copies complete.
    auto produce = [&](int j, int s) {
        const int k0 = j * BK;
        const bool fullw = (j < NCHUNK - 1);   // last chunk is 16-wide
        const uint32_t sb = dbase + s * STAGE;
        #pragma unroll
        for (int i = 0; i < 4; i++) {          // A: 128 rows x 8 cols of 16B
            const int idx = tid + 256 * i;
            const int row = idx >> 3, c = idx & 7;
            if (fullw || c < 2)
                cp16(sb + row * ROWB + c * 16,
                     g_Ah + (size_t)(m0 + row) * kKpad + k0 + c * 8);
        }
        #pragma unroll
        for (int i = 0; i < 6; i++) {          // B: 192 rows x 8 cols
            const int idx = tid + 256 * i;
            const int row = idx >> 3, c = idx & 7;
            if (fullw || c < 2)
                cp16(sb + ARR_A + row * ROWB + c * 16,
                     g_Wh + (size_t)(n0 + row) * kKpad + k0 + c * 8);
        }
        cp_mbar_arrive_noinc(sbase + 8 * s);
    };

    // ldmatrix per-thread offsets
    const int sel = lane >> 3, li = lane & 7;
    const int aRow = (sel & 1) * 8 + li;
    const int aC16 = (sel >> 1) * 16;
    const int bRow = (sel >> 1) * 8 + li;
    const int bC16 = (sel & 1) * 16;

    float acc[4][6][4];
    #pragma unroll
    for (int i = 0; i < 4; i++)
        #pragma unroll
        for (int j = 0; j < 6; j++)
            #pragma unroll
            for (int q = 0; q < 4; q++) acc[i][j][q] = 0.f;

    produce(0, 0);
    produce(1, 1);
    produce(2, 2);

    auto do_ks = [&](uint32_t aBase, uint32_t bBase, int ks) {
        uint32_t af[4][4], bf[3][4];
        #pragma unroll
        for (int mt = 0; mt < 4; mt++)
            ldsm4(af[mt], aBase + mt * 16 * ROWB + ks * 32);
        #pragma unroll
        for (int bt = 0; bt < 3; bt++)
            ldsm4(bf[bt], bBase + bt * 16 * ROWB + ks * 32);
        #pragma unroll
        for (int mt = 0; mt < 4; mt++)
            #pragma unroll
            for (int nt = 0; nt < 6; nt++)
                mma16816(acc[mt][nt], af[mt], &bf[nt >> 1][(nt & 1) * 2]);
    };

    #pragma unroll 1
    for (int j = 0; j < NCHUNK; j++) {
        const int s = j & 3;

        // prefetch chunk j+3 (stage previously held chunk j-1)
        const int jp = j + 3;
        if (jp < NCHUNK) {
            const int sp = jp & 3;
            if (jp >= NSTG)
                mbar_wait(sbase + 32 + 8 * sp, ((jp >> 2) - 1) & 1);
            produce(jp, sp);
        }

        // consume chunk j
        mbar_wait(sbase + 8 * s, (j >> 2) & 1);
        const uint32_t st = dbase + s * STAGE;
        const uint32_t aBase = st + (warp_m + aRow) * ROWB + aC16;
        const uint32_t bBase = st + ARR_A + (warp_n + bRow) * ROWB + bC16;
        if (j < NCHUNK - 1) {
            #pragma unroll
            for (int ks = 0; ks < 4; ks++) do_ks(aBase, bBase, ks);
        } else {
            do_ks(aBase, bBase, 0);            // partial chunk: 16 wide
        }
        mbar_arrive(sbase + 32 + 8 * s);       // stage free
    }

    // ---------------- epilogue: + bias + pos_emb[pos[m]] --------------------
    const int r = lane >> 2, cg = lane & 3;
    #pragma unroll
    for (int mt = 0; mt < 4; mt++) {
        #pragma unroll
        for (int h = 0; h < 2; h++) {
            const int m = m0 + warp_m + mt * 16 + h * 8 + r;
            const float* per = pe + (size_t)g_pos[m] * kD;
            float* orow = out + (size_t)m * kD;
            #pragma unroll
            for (int nt = 0; nt < 6; nt++) {
                const int n = n0 + warp_n + nt * 8 + cg * 2;
                const float2 p = *reinterpret_cast<const float2*>(per + n);
                const float2 bv = *reinterpret_cast<const float2*>(bias + n);
                float2 v;
                v.x = acc[mt][nt][h * 2 + 0] + p.x + bv.x;
                v.y = acc[mt][nt][h * 2 + 1] + p.y + bv.y;
                *reinterpret_cast<float2*>(orow + n) = v;
            }
        }
    }
}

// ---------------------------------------------------------------------------
extern "C" void kernel_launch(void* const* d_in, const int* in_sizes, int n_in,
                              void* d_out, int out_size) {
    const float* pix          = (const float*)d_in[0];
    const unsigned char* mask = (const unsigned char*)d_in[1];
    const float* wgt          = (const float*)d_in[2];
    const float* bias         = (const float*)d_in[3];
    const float* pe           = (const float*)d_in[4];
    float* out                = (float*)d_out;

    pos_kernel<<<kB, 128>>>(mask);
    prep_w<<<720, 256>>>(wgt);
    prep_pad<<<128, 256>>>();
    dim3 agrid(kB, kNPS);
    prep_a<<<agrid, 256>>>(pix);

    static bool attr_set = false;
    if (!attr_set) {
        cudaFuncSetAttribute(gemm_kernel,
                             cudaFuncAttributeMaxDynamicSharedMemorySize,
                             SMEM_SZ);
        attr_set = true;
    }
    dim3 grid(kM / BM, kD / BN);  // (169, 6)
    gemm_kernel<<<grid, 256, SMEM_SZ>>>(bias, pe, out);
}

// round 13
// speedup vs baseline: 4.6246x; 1.0019x over previous
#include <cuda_runtime.h>
#include <cuda_fp16.h>
#include <cstdint>

// ===========================================================================
// Idefics3VisionEmbeddings via single-term fp16 mma.sync (base sm_103 ISA).
//   out[m,n] = sum_k A[m,k]*W[n,k] + bias[n] + pos_emb[pos[m], n]
//   M=21632 (=169*128 exact), N=1152 (=6*192), K=588 (pad 592)
// fp16 inputs (rn), fp32 accumulate. Norm-ratio error ~3e-4 < 1e-3.
// Block tile 128x192, warp tile 64x48 (8 warps), BK=64 (last chunk 16),
// 4-stage mbarrier ring + FRAGMENT DOUBLE-BUFFERING: LDSM batch for step
// ks+1 issues before the MMAs of step ks, hiding shared-mem latency.
// ===========================================================================

namespace {
constexpr int kNPS = 26, kPatch = 14, kB = 32, kC = 3, kHW = 364, kD = 1152;
constexpr int kP = kNPS * kNPS;           // 676
constexpr int kK = kC * kPatch * kPatch;  // 588
constexpr int kM = kB * kP;               // 21632
constexpr int kKpad = 592;                // 37 * 16

constexpr int BM = 128, BN = 192, BK = 64;
constexpr int NCHUNK = 10;                // 9 full (64) + 1 partial (16)

// smem rows: 64 fp16 = 128 B, padded to 144 B (16B-aligned; conflict-free)
constexpr int ROWB = 144;
constexpr int ARR_A = BM * ROWB;          // 18432 B
constexpr int ARR_B = BN * ROWB;          // 27648 B
constexpr int STAGE = ARR_A + ARR_B;      // 46080 B
constexpr int NSTG = 4;
constexpr int BARS = 64;                  // barrier block (full[4], empty[4])
constexpr int SMEM_SZ = BARS + NSTG * STAGE;
}  // namespace

// -------------------- device scratch (no cudaMalloc allowed) ---------------
__device__ __align__(256) __half g_Ah[(size_t)kM * kKpad];
__device__ __align__(256) __half g_Wh[(size_t)kD * kKpad];
__device__ int g_pos[kM];

// -------------------- helpers ----------------------------------------------
__device__ __forceinline__ uint32_t smem_u32(const void* p) {
    uint32_t a;
    asm("{ .reg .u64 t; cvta.to.shared.u64 t, %1; cvt.u32.u64 %0, t; }"
        : "=r"(a) : "l"(p));
    return a;
}
__device__ __forceinline__ void cp16(uint32_t dst, const void* src) {
    asm volatile("cp.async.cg.shared.global [%0], [%1], 16;"
                 :: "r"(dst), "l"(src) : "memory");
}
__device__ __forceinline__ void cp_mbar_arrive_noinc(uint32_t bar) {
    asm volatile("cp.async.mbarrier.arrive.noinc.shared::cta.b64 [%0];"
                 :: "r"(bar) : "memory");
}
__device__ __forceinline__ void mbar_init(uint32_t a, uint32_t cnt) {
    asm volatile("mbarrier.init.shared.b64 [%0], %1;" :: "r"(a), "r"(cnt) : "memory");
}
__device__ __forceinline__ void mbar_arrive(uint32_t a) {
    asm volatile("mbarrier.arrive.shared.b64 _, [%0];" :: "r"(a) : "memory");
}
__device__ __forceinline__ void mbar_wait(uint32_t a, uint32_t parity) {
    asm volatile(
        "{\n .reg .pred P;\n"
        "WL_%=:\n"
        " mbarrier.try_wait.parity.shared.b64 P, [%0], %1, 0x989680;\n"
        " @P bra WD_%=;\n"
        " bra WL_%=;\n"
        "WD_%=:\n}" :: "r"(a), "r"(parity) : "memory");
}
__device__ __forceinline__ void ldsm4(uint32_t* r, uint32_t addr) {
    asm volatile("ldmatrix.sync.aligned.m8n8.x4.shared.b16 {%0,%1,%2,%3}, [%4];"
                 : "=r"(r[0]), "=r"(r[1]), "=r"(r[2]), "=r"(r[3]) : "r"(addr));
}
__device__ __forceinline__ void mma16816(float* c, const uint32_t* a,
                                         const uint32_t* b) {
    asm volatile(
        "mma.sync.aligned.m16n8k16.row.col.f32.f16.f16.f32 "
        "{%0,%1,%2,%3}, {%4,%5,%6,%7}, {%8,%9}, {%0,%1,%2,%3};"
        : "+f"(c[0]), "+f"(c[1]), "+f"(c[2]), "+f"(c[3])
        : "r"(a[0]), "r"(a[1]), "r"(a[2]), "r"(a[3]), "r"(b[0]), "r"(b[1]));
}

// ---------------------------------------------------------------------------
// Position ids (exact fp32 replica of the reference). Mask dtype auto-detect:
// byte 1 nonzero => u8/bool layout (nb_w>=13 guarantees mask[0][0][1]==1).
// ---------------------------------------------------------------------------
__global__ void pos_kernel(const unsigned char* __restrict__ mraw) {
    const int b = blockIdx.x;
    const int t = threadIdx.x;
    __shared__ int s_bh[kNPS], s_bw[kNPS];
    __shared__ int s_nbh, s_nbw;

    const bool is_u8 = (mraw[1] != 0);
    auto mval = [&](int idx) -> int {
        return is_u8 ? (int)mraw[idx] : (int)mraw[4 * (size_t)idx];
    };
    const int base = b * kP;
    if (t == 0) {
        int nh = 0, nw = 0;
        for (int i = 0; i < kNPS; i++) nh += (mval(base + i * kNPS) != 0);
        for (int j = 0; j < kNPS; j++) nw += (mval(base + j) != 0);
        s_nbh = nh; s_nbw = nw;
    }
    __syncthreads();
    if (t < kNPS) {
        const float eps = 1.0f - 1e-6f;
        const float fh = ((float)t / (float)s_nbh) * eps;
        const float fw = ((float)t / (float)s_nbw) * eps;
        int ch = 0, cw = 0;
        #pragma unroll
        for (int j = 1; j < kNPS; j++) {
            const float bnd = (float)j / (float)kNPS;
            ch += (bnd <= fh) ? 1 : 0;
            cw += (bnd <= fw) ? 1 : 0;
        }
        s_bh[t] = ch; s_bw[t] = cw;
    }
    __syncthreads();
    for (int p = t; p < kP; p += blockDim.x) {
        const int ph = p / kNPS;
        const int pw = p - ph * kNPS;
        g_pos[base + p] = (mval(base + p) != 0) ? (s_bh[ph] * kNPS + s_bw[pw]) : 0;
    }
}

// ---------------------------------------------------------------------------
// Prep A: one block per (b, ph) strip. Coalesced 364-float pixel row reads.
// ---------------------------------------------------------------------------
__global__ void prep_a(const float* __restrict__ pix) {
    const int b = blockIdx.x, ph = blockIdx.y;
    const float* src = pix + (size_t)b * (kC * kHW * kHW)
                       + (size_t)(ph * kPatch) * kHW;
    const int mbase = b * kP + ph * kNPS;
    constexpr int TOT = kC * kPatch * (kHW / 2);  // 7644 half2 elements
    for (int e = threadIdx.x; e < TOT; e += blockDim.x) {
        const int rowid = e / (kHW / 2);          // c*14 + ky
        const int x2 = e - rowid * (kHW / 2);
        const int c = rowid / kPatch;
        const int ky = rowid - c * kPatch;
        const int x = x2 * 2;
        const int pw = x / kPatch;
        const int kx = x - pw * kPatch;
        const float2 v = *reinterpret_cast<const float2*>(
            src + (size_t)c * (kHW * kHW) + ky * kHW + x);
        const int m = mbase + pw;
        const int k = c * (kPatch * kPatch) + ky * kPatch + kx;
        *reinterpret_cast<__half2*>(g_Ah + (size_t)m * kKpad + k) =
            __floats2half2_rn(v.x, v.y);
    }
}

// Zero the K padding [588, 592) of g_Ah.
__global__ void prep_pad() {
    const int total = kM * 2;
    for (int idx = blockIdx.x * blockDim.x + threadIdx.x; idx < total;
         idx += gridDim.x * blockDim.x) {
        const int m = idx >> 1;
        const int k = kK + (idx & 1) * 2;
        *reinterpret_cast<__half2*>(g_Ah + (size_t)m * kKpad + k) =
            __float2half2_rn(0.f);
    }
}

__global__ void prep_w(const float* __restrict__ wgt) {
    const int total = kD * kKpad;
    for (int idx = blockIdx.x * blockDim.x + threadIdx.x; idx < total;
         idx += gridDim.x * blockDim.x) {
        const int n = idx / kKpad;
        const int k = idx - n * kKpad;
        g_Wh[idx] = __float2half_rn((k < kK) ? wgt[(size_t)n * kK + k] : 0.f);
    }
}

// ---------------------------------------------------------------------------
// GEMM: 128x192 tile, warp tile 64x48, 4-stage mbarrier ring, 8 warps,
// double-buffered fragments.
// ---------------------------------------------------------------------------
__global__ void __launch_bounds__(256, 1)
gemm_kernel(const float* __restrict__ bias,
            const float* __restrict__ pe,
            float* __restrict__ out) {
    extern __shared__ char smem[];
    const uint32_t sbase = smem_u32(smem);
    const uint32_t dbase = sbase + BARS;
    const int tid = threadIdx.x;
    const int wid = tid >> 5;
    const int lane = tid & 31;

    const int m0 = blockIdx.x * BM;
    const int n0 = blockIdx.y * BN;

    const int warp_m = (wid & 1) * 64;   // 2 warps along M
    const int warp_n = (wid >> 1) * 48;  // 4 warps along N

    if (tid == 0) {
        #pragma unroll
        for (int s = 0; s < NSTG; s++) {
            mbar_init(sbase + 8 * s, 256);
            mbar_init(sbase + 32 + 8 * s, 256);
        }
    }
    __syncthreads();

    auto produce = [&](int j, int s) {
        const int k0 = j * BK;
        const bool fullw = (j < NCHUNK - 1);   // last chunk is 16-wide
        const uint32_t sb = dbase + s * STAGE;
        #pragma unroll
        for (int i = 0; i < 4; i++) {          // A: 128 rows x 8 cols of 16B
            const int idx = tid + 256 * i;
            const int row = idx >> 3, c = idx & 7;
            if (fullw || c < 2)
                cp16(sb + row * ROWB + c * 16,
                     g_Ah + (size_t)(m0 + row) * kKpad + k0 + c * 8);
        }
        #pragma unroll
        for (int i = 0; i < 6; i++) {          // B: 192 rows x 8 cols
            const int idx = tid + 256 * i;
            const int row = idx >> 3, c = idx & 7;
            if (fullw || c < 2)
                cp16(sb + ARR_A + row * ROWB + c * 16,
                     g_Wh + (size_t)(n0 + row) * kKpad + k0 + c * 8);
        }
        cp_mbar_arrive_noinc(sbase + 8 * s);
    };

    // ldmatrix per-thread offsets
    const int sel = lane >> 3, li = lane & 7;
    const int aRow = (sel & 1) * 8 + li;
    const int aC16 = (sel >> 1) * 16;
    const int bRow = (sel >> 1) * 8 + li;
    const int bC16 = (sel & 1) * 16;

    float acc[4][6][4];
    #pragma unroll
    for (int i = 0; i < 4; i++)
        #pragma unroll
        for (int j = 0; j < 6; j++)
            #pragma unroll
            for (int q = 0; q < 4; q++) acc[i][j][q] = 0.f;

    produce(0, 0);
    produce(1, 1);
    produce(2, 2);

    // double-buffered fragments
    uint32_t af[2][4][4], bf[2][3][4];

    auto load_frags = [&](uint32_t aBase, uint32_t bBase, int ks, int buf) {
        #pragma unroll
        for (int mt = 0; mt < 4; mt++)
            ldsm4(af[buf][mt], aBase + mt * 16 * ROWB + ks * 32);
        #pragma unroll
        for (int bt = 0; bt < 3; bt++)
            ldsm4(bf[buf][bt], bBase + bt * 16 * ROWB + ks * 32);
    };
    auto do_mma = [&](int buf) {
        #pragma unroll
        for (int mt = 0; mt < 4; mt++)
            #pragma unroll
            for (int nt = 0; nt < 6; nt++)
                mma16816(acc[mt][nt], af[buf][mt], &bf[buf][nt >> 1][(nt & 1) * 2]);
    };

    #pragma unroll 1
    for (int j = 0; j < NCHUNK; j++) {
        const int s = j & 3;

        // prefetch chunk j+3 (stage previously held chunk j-1)
        const int jp = j + 3;
        if (jp < NCHUNK) {
            const int sp = jp & 3;
            if (jp >= NSTG)
                mbar_wait(sbase + 32 + 8 * sp, ((jp >> 2) - 1) & 1);
            produce(jp, sp);
        }

        // consume chunk j with fragment double-buffering
        mbar_wait(sbase + 8 * s, (j >> 2) & 1);
        const uint32_t st = dbase + s * STAGE;
        const uint32_t aBase = st + (warp_m + aRow) * ROWB + aC16;
        const uint32_t bBase = st + ARR_A + (warp_n + bRow) * ROWB + bC16;
        if (j < NCHUNK - 1) {
            load_frags(aBase, bBase, 0, 0);
            #pragma unroll
            for (int ks = 0; ks < 4; ks++) {
                if (ks < 3) load_frags(aBase, bBase, ks + 1, (ks + 1) & 1);
                do_mma(ks & 1);
            }
        } else {
            load_frags(aBase, bBase, 0, 0);
            do_mma(0);                         // partial chunk: 16 wide
        }
        mbar_arrive(sbase + 32 + 8 * s);       // stage free
    }

    // ---------------- epilogue: + bias + pos_emb[pos[m]] --------------------
    const int r = lane >> 2, cg = lane & 3;
    #pragma unroll
    for (int mt = 0; mt < 4; mt++) {
        #pragma unroll
        for (int h = 0; h < 2; h++) {
            const int m = m0 + warp_m + mt * 16 + h * 8 + r;
            const float* per = pe + (size_t)g_pos[m] * kD;
            float* orow = out + (size_t)m * kD;
            #pragma unroll
            for (int nt = 0; nt < 6; nt++) {
                const int n = n0 + warp_n + nt * 8 + cg * 2;
                const float2 p = *reinterpret_cast<const float2*>(per + n);
                const float2 bv = *reinterpret_cast<const float2*>(bias + n);
                float2 v;
                v.x = acc[mt][nt][h * 2 + 0] + p.x + bv.x;
                v.y = acc[mt][nt][h * 2 + 1] + p.y + bv.y;
                *reinterpret_cast<float2*>(orow + n) = v;
            }
        }
    }
}

// ---------------------------------------------------------------------------
extern "C" void kernel_launch(void* const* d_in, const int* in_sizes, int n_in,
                              void* d_out, int out_size) {
    const float* pix          = (const float*)d_in[0];
    const unsigned char* mask = (const unsigned char*)d_in[1];
    const float* wgt          = (const float*)d_in[2];
    const float* bias         = (const float*)d_in[3];
    const float* pe           = (const float*)d_in[4];
    float* out                = (float*)d_out;

    pos_kernel<<<kB, 128>>>(mask);
    prep_w<<<720, 256>>>(wgt);
    prep_pad<<<128, 256>>>();
    dim3 agrid(kB, kNPS);
    prep_a<<<agrid, 256>>>(pix);

    static bool attr_set = false;
    if (!attr_set) {
        cudaFuncSetAttribute(gemm_kernel,
                             cudaFuncAttributeMaxDynamicSharedMemorySize,
                             SMEM_SZ);
        attr_set = true;
    }
    dim3 grid(kM / BM, kD / BN);  // (169, 6)
    gemm_kernel<<<grid, 256, SMEM_SZ>>>(bias, pe, out);
}